// round 10
// baseline (speedup 1.0000x reference)
#include <cuda_runtime.h>
#include <cuda_bf16.h>
#include <math.h>
#include <stdint.h>

// Problem constants
#define BATCH 2
#define SEQ   2048
#define HID   4096
#define NH    32
#define KVH   8
#define HD    128
#define NREP  (NH / KVH)          // 4
#define MROWS (BATCH * SEQ)       // 4096
#define KVDIM (KVH * HD)          // 1024

// ---------------------------------------------------------------------------
// Scratch (device globals; no runtime allocation allowed)
// ---------------------------------------------------------------------------
__device__ float g_q[(size_t)MROWS * NH * HD];      // 64 MB
__device__ float g_k[(size_t)MROWS * KVH * HD];     // 16 MB
__device__ float g_v[(size_t)MROWS * KVH * HD];     // 16 MB
__device__ float g_attn[(size_t)MROWS * HID];       // 64 MB
__device__ float g_cos[(size_t)MROWS * (HD / 2)];
__device__ float g_sin[(size_t)MROWS * (HD / 2)];

// ---------------------------------------------------------------------------
// RoPE cos/sin table. position = row % SEQ (arange broadcast over batch).
// fp64 trig: accurate regardless of --use_fast_math.
// ---------------------------------------------------------------------------
__global__ void rope_table_kernel(float* __restrict__ cosT,
                                  float* __restrict__ sinT) {
    int bs = blockIdx.x;
    int d  = threadIdx.x;      // [0, 64)
    double p = (double)(bs % SEQ);
    double inv_freq = exp(-((double)(2 * d) / 128.0) * log(10000.0));
    double a = p * inv_freq;
    cosT[(size_t)bs * 64 + d] = (float)cos(a);
    sinT[(size_t)bs * 64 + d] = (float)sin(a);
}

// ---------------------------------------------------------------------------
// RoPE apply: x layout [B*S, heads, 128], in-place
// ---------------------------------------------------------------------------
__global__ void rope_apply_kernel(float* __restrict__ x,
                                  const float* __restrict__ cosT,
                                  const float* __restrict__ sinT,
                                  int heads) {
    long long i = (long long)blockIdx.x * blockDim.x + threadIdx.x;
    long long total = (long long)MROWS * heads * 64;
    if (i >= total) return;
    int d = (int)(i & 63);
    long long t = i >> 6;
    int h = (int)(t % heads);
    long long bs = t / heads;
    float c = cosT[bs * 64 + d];
    float s = sinT[bs * 64 + d];
    float* p = x + ((size_t)bs * heads + h) * HD;
    float x1 = p[d];
    float x2 = p[d + 64];
    p[d]      = x1 * c - x2 * s;
    p[d + 64] = x2 * c + x1 * s;
}

// ---------------------------------------------------------------------------
// tf32 helpers
// ---------------------------------------------------------------------------
__device__ __forceinline__ uint32_t f2tf32(float f) {
    uint32_t r;
    asm("cvt.rna.tf32.f32 %0, %1;" : "=r"(r) : "f"(f));
    return r;
}

// Split fp32 into tf32 hi + tf32 lo (hi+lo ~ 21-bit mantissa coverage)
__device__ __forceinline__ void split_tf32(float x, uint32_t& h, uint32_t& l) {
    uint32_t hh = f2tf32(x);
    h = hh;
    l = f2tf32(x - __uint_as_float(hh));
}

__device__ __forceinline__ void mma_tf32(float c[4], const uint32_t a[4],
                                         const uint32_t b[2]) {
    asm volatile(
        "mma.sync.aligned.m16n8k8.row.col.f32.tf32.tf32.f32 "
        "{%0,%1,%2,%3}, {%4,%5,%6,%7}, {%8,%9}, {%0,%1,%2,%3};"
        : "+f"(c[0]), "+f"(c[1]), "+f"(c[2]), "+f"(c[3])
        : "r"(a[0]), "r"(a[1]), "r"(a[2]), "r"(a[3]), "r"(b[0]), "r"(b[1]));
}

// ---------------------------------------------------------------------------
// Plain tf32 GEMM: C[M,N] = A[M,K] @ B[K,N], row-major.
// 128x128 CTA tile, BK=32, 256 threads (8 warps), warp tile 64x32.
// ---------------------------------------------------------------------------
#define AS_STRIDE 36    // 32 + 4  -> conflict-free A-fragment LDS
#define BS_STRIDE 136   // 128 + 8 -> conflict-free B-fragment LDS

__global__ __launch_bounds__(256)
void tgemm_kernel(const float* __restrict__ A, const float* __restrict__ B,
                  float* __restrict__ C, int M, int N, int K) {
    __shared__ uint32_t As[128 * AS_STRIDE];   // [m][k]
    __shared__ uint32_t Bs[32 * BS_STRIDE];    // [k][n]

    const int tid  = threadIdx.x;
    const int lane = tid & 31;
    const int warp = tid >> 5;
    const int wm0 = (warp & 1) * 64;
    const int wn0 = (warp >> 1) * 32;
    const int m0 = blockIdx.y * 128;
    const int n0 = blockIdx.x * 128;
    const int lq = lane >> 2;
    const int lr = lane & 3;

    float c[4][4][4];
#pragma unroll
    for (int mi = 0; mi < 4; mi++)
#pragma unroll
        for (int ni = 0; ni < 4; ni++)
#pragma unroll
            for (int r = 0; r < 4; r++) c[mi][ni][r] = 0.0f;

    for (int kt = 0; kt < K; kt += 32) {
#pragma unroll
        for (int l = 0; l < 4; l++) {
            int idx = tid + l * 256;
            int row = idx >> 3;
            int cc  = (idx & 7) * 4;
            float4 v = *(const float4*)(A + (size_t)(m0 + row) * K + kt + cc);
            uint32_t* p = &As[row * AS_STRIDE + cc];
            p[0] = f2tf32(v.x); p[1] = f2tf32(v.y);
            p[2] = f2tf32(v.z); p[3] = f2tf32(v.w);
        }
#pragma unroll
        for (int l = 0; l < 4; l++) {
            int idx = tid + l * 256;
            int row = idx >> 5;
            int cc  = (idx & 31) * 4;
            float4 v = *(const float4*)(B + (size_t)(kt + row) * N + n0 + cc);
            uint32_t* p = &Bs[row * BS_STRIDE + cc];
            p[0] = f2tf32(v.x); p[1] = f2tf32(v.y);
            p[2] = f2tf32(v.z); p[3] = f2tf32(v.w);
        }
        __syncthreads();

#pragma unroll
        for (int kk = 0; kk < 32; kk += 8) {
            uint32_t a[4][4], b[4][2];
#pragma unroll
            for (int mi = 0; mi < 4; mi++) {
                int rb = wm0 + mi * 16 + lq;
                a[mi][0] = As[rb * AS_STRIDE + kk + lr];
                a[mi][1] = As[(rb + 8) * AS_STRIDE + kk + lr];
                a[mi][2] = As[rb * AS_STRIDE + kk + lr + 4];
                a[mi][3] = As[(rb + 8) * AS_STRIDE + kk + lr + 4];
            }
#pragma unroll
            for (int ni = 0; ni < 4; ni++) {
                int cb = wn0 + ni * 8 + lq;
                b[ni][0] = Bs[(kk + lr) * BS_STRIDE + cb];
                b[ni][1] = Bs[(kk + lr + 4) * BS_STRIDE + cb];
            }
#pragma unroll
            for (int mi = 0; mi < 4; mi++)
#pragma unroll
                for (int ni = 0; ni < 4; ni++)
                    mma_tf32(c[mi][ni], a[mi], b[ni]);
        }
        __syncthreads();
    }

#pragma unroll
    for (int mi = 0; mi < 4; mi++) {
#pragma unroll
        for (int ni = 0; ni < 4; ni++) {
            int r   = m0 + wm0 + mi * 16 + lq;
            int col = n0 + wn0 + ni * 8 + lr * 2;
            *(float2*)(C + (size_t)r * N + col) =
                make_float2(c[mi][ni][0], c[mi][ni][1]);
            *(float2*)(C + (size_t)(r + 8) * N + col) =
                make_float2(c[mi][ni][2], c[mi][ni][3]);
        }
    }
}

// ---------------------------------------------------------------------------
// Compensated tf32 GEMM (hi/lo split, 3 MMAs): ~fp32 accuracy.
// Same tiling as tgemm_kernel. Dynamic smem: 71680 bytes.
// ---------------------------------------------------------------------------
#define CGEMM_SMEM_BYTES 71680

__global__ __launch_bounds__(256)
void tgemm_comp_kernel(const float* __restrict__ A, const float* __restrict__ B,
                       float* __restrict__ C, int M, int N, int K) {
    extern __shared__ uint32_t csm[];
    uint32_t* Ash = csm;                     // [128][36]
    uint32_t* Asl = Ash + 128 * AS_STRIDE;   // 4608
    uint32_t* Bsh = Asl + 128 * AS_STRIDE;   // [32][136]
    uint32_t* Bsl = Bsh + 32 * BS_STRIDE;    // 4352

    const int tid  = threadIdx.x;
    const int lane = tid & 31;
    const int warp = tid >> 5;
    const int wm0 = (warp & 1) * 64;
    const int wn0 = (warp >> 1) * 32;
    const int m0 = blockIdx.y * 128;
    const int n0 = blockIdx.x * 128;
    const int lq = lane >> 2;
    const int lr = lane & 3;

    float c[4][4][4];
#pragma unroll
    for (int mi = 0; mi < 4; mi++)
#pragma unroll
        for (int ni = 0; ni < 4; ni++)
#pragma unroll
            for (int r = 0; r < 4; r++) c[mi][ni][r] = 0.0f;

    for (int kt = 0; kt < K; kt += 32) {
#pragma unroll
        for (int l = 0; l < 4; l++) {
            int idx = tid + l * 256;
            int row = idx >> 3;
            int cc  = (idx & 7) * 4;
            float4 v = *(const float4*)(A + (size_t)(m0 + row) * K + kt + cc);
            uint32_t *ph = &Ash[row * AS_STRIDE + cc], *pl = &Asl[row * AS_STRIDE + cc];
            split_tf32(v.x, ph[0], pl[0]); split_tf32(v.y, ph[1], pl[1]);
            split_tf32(v.z, ph[2], pl[2]); split_tf32(v.w, ph[3], pl[3]);
        }
#pragma unroll
        for (int l = 0; l < 4; l++) {
            int idx = tid + l * 256;
            int row = idx >> 5;
            int cc  = (idx & 31) * 4;
            float4 v = *(const float4*)(B + (size_t)(kt + row) * N + n0 + cc);
            uint32_t *ph = &Bsh[row * BS_STRIDE + cc], *pl = &Bsl[row * BS_STRIDE + cc];
            split_tf32(v.x, ph[0], pl[0]); split_tf32(v.y, ph[1], pl[1]);
            split_tf32(v.z, ph[2], pl[2]); split_tf32(v.w, ph[3], pl[3]);
        }
        __syncthreads();

#pragma unroll
        for (int kk = 0; kk < 32; kk += 8) {
            uint32_t ah[4][4], al[4][4], bh[4][2], bl[4][2];
#pragma unroll
            for (int mi = 0; mi < 4; mi++) {
                int rb = wm0 + mi * 16 + lq;
                int o0 = rb * AS_STRIDE + kk + lr;
                int o1 = (rb + 8) * AS_STRIDE + kk + lr;
                ah[mi][0] = Ash[o0];     ah[mi][1] = Ash[o1];
                ah[mi][2] = Ash[o0 + 4]; ah[mi][3] = Ash[o1 + 4];
                al[mi][0] = Asl[o0];     al[mi][1] = Asl[o1];
                al[mi][2] = Asl[o0 + 4]; al[mi][3] = Asl[o1 + 4];
            }
#pragma unroll
            for (int ni = 0; ni < 4; ni++) {
                int cb = wn0 + ni * 8 + lq;
                int o0 = (kk + lr) * BS_STRIDE + cb;
                int o1 = (kk + lr + 4) * BS_STRIDE + cb;
                bh[ni][0] = Bsh[o0]; bh[ni][1] = Bsh[o1];
                bl[ni][0] = Bsl[o0]; bl[ni][1] = Bsl[o1];
            }
#pragma unroll
            for (int mi = 0; mi < 4; mi++)
#pragma unroll
                for (int ni = 0; ni < 4; ni++) {
                    mma_tf32(c[mi][ni], ah[mi], bh[ni]);
                    mma_tf32(c[mi][ni], al[mi], bh[ni]);
                    mma_tf32(c[mi][ni], ah[mi], bl[ni]);
                }
        }
        __syncthreads();
    }

#pragma unroll
    for (int mi = 0; mi < 4; mi++) {
#pragma unroll
        for (int ni = 0; ni < 4; ni++) {
            int r   = m0 + wm0 + mi * 16 + lq;
            int col = n0 + wn0 + ni * 8 + lr * 2;
            *(float2*)(C + (size_t)r * N + col) =
                make_float2(c[mi][ni][0], c[mi][ni][1]);
            *(float2*)(C + (size_t)(r + 8) * N + col) =
                make_float2(c[mi][ni][2], c[mi][ni][3]);
        }
    }
}

// ---------------------------------------------------------------------------
// Flash attention, tensor-core tf32.
// BM=128, BN=64, D=128. Grid (SEQ/128, NH, BATCH), 256 threads (8 warps),
// warp owns 16 rows. S = QK^T compensated (3 MMAs, Q/K pre-split hi/lo in
// smem; zero ALU in hot loop). PV plain single-tf32 (1 MMA; error absorbed by
// compensated wv/wo GEMMs).
// Dynamic smem (floats):
//   Qh[128][132] 16896 | Ql 16896 | Kh[64][36] 2304 | Kl 2304
//   Ps[128][68] 8704   | Vt[128][36] 4608           -> 51712 fl = 206848 B
// ---------------------------------------------------------------------------
#define ATTN_SMEM_BYTES 206848

__global__ __launch_bounds__(256)
void attn_mma_kernel(const float* __restrict__ Q, const float* __restrict__ K,
                     const float* __restrict__ V, float* __restrict__ O) {
    extern __shared__ float sm[];
    float* Qh = sm;              // [128][132]
    float* Ql = Qh + 16896;
    float* Kh = Ql + 16896;      // [64][36]
    float* Kl = Kh + 2304;
    float* Ps = Kl + 2304;       // [128][68] single tf32
    float* Vt = Ps + 8704;       // [128][36] single tf32, [d][j]

    const int q0g = blockIdx.x * 128;
    const int h   = blockIdx.y;
    const int b   = blockIdx.z;
    const int kvh = h / NREP;
    const float* Qb = Q + ((size_t)b * SEQ * NH + h) * HD;
    const float* Kb = K + ((size_t)b * SEQ * KVH + kvh) * HD;
    const float* Vb = V + ((size_t)b * SEQ * KVH + kvh) * HD;
    float* Ob = O + (size_t)b * SEQ * HID + (size_t)h * HD;

    const int tid  = threadIdx.x;
    const int lane = tid & 31;
    const int warp = tid >> 5;
    const int wm   = warp * 16;
    const int lq   = lane >> 2;
    const int lr   = lane & 3;
    const float scale = 0.08838834764831845f;  // 1/sqrt(128)

    // ---- load Q tile once: scale + hi/lo split ----
#pragma unroll
    for (int l = 0; l < 16; l++) {
        int idx = tid + l * 256;
        int row = idx >> 5;
        int c4  = (idx & 31) * 4;
        float4 v = *(const float4*)(Qb + (size_t)(q0g + row) * (NH * HD) + c4);
        float* ph = Qh + row * 132 + c4;
        float* pl = Ql + row * 132 + c4;
        uint32_t hh, ll;
        split_tf32(v.x * scale, hh, ll); ph[0] = __uint_as_float(hh); pl[0] = __uint_as_float(ll);
        split_tf32(v.y * scale, hh, ll); ph[1] = __uint_as_float(hh); pl[1] = __uint_as_float(ll);
        split_tf32(v.z * scale, hh, ll); ph[2] = __uint_as_float(hh); pl[2] = __uint_as_float(ll);
        split_tf32(v.w * scale, hh, ll); ph[3] = __uint_as_float(hh); pl[3] = __uint_as_float(ll);
    }

    float oc[16][4];
#pragma unroll
    for (int nt = 0; nt < 16; nt++)
#pragma unroll
        for (int r = 0; r < 4; r++) oc[nt][r] = 0.0f;
    float m_i[2] = {-1e30f, -1e30f};
    float l_i[2] = {0.0f, 0.0f};

    const int dcol = tid & 127;
    const int jh   = (tid >> 7) * 16;

    const int jmax = q0g + 64;
    for (int j0 = 0; j0 <= jmax; j0 += 64) {
        // ================== S = Qscaled @ K^T  (128x64, K=128) ============
        float sc[8][4];
#pragma unroll
        for (int nt = 0; nt < 8; nt++)
#pragma unroll
            for (int r = 0; r < 4; r++) sc[nt][r] = 0.0f;

        for (int kc = 0; kc < 4; kc++) {
            __syncthreads();
            // load K chunk (64 x 32), hi/lo split
#pragma unroll
            for (int l = 0; l < 2; l++) {
                int idx = tid + l * 256;
                int row = idx >> 3;
                int c4  = (idx & 7) * 4;
                float4 v = *(const float4*)(Kb + (size_t)(j0 + row) * KVDIM + kc * 32 + c4);
                float* ph = Kh + row * 36 + c4;
                float* pl = Kl + row * 36 + c4;
                uint32_t hh, ll;
                split_tf32(v.x, hh, ll); ph[0] = __uint_as_float(hh); pl[0] = __uint_as_float(ll);
                split_tf32(v.y, hh, ll); ph[1] = __uint_as_float(hh); pl[1] = __uint_as_float(ll);
                split_tf32(v.z, hh, ll); ph[2] = __uint_as_float(hh); pl[2] = __uint_as_float(ll);
                split_tf32(v.w, hh, ll); ph[3] = __uint_as_float(hh); pl[3] = __uint_as_float(ll);
            }
            __syncthreads();
#pragma unroll
            for (int ks = 0; ks < 4; ks++) {
                int kq = kc * 32 + ks * 8;
                int a0 = (wm + lq) * 132 + kq + lr;
                int a1 = (wm + lq + 8) * 132 + kq + lr;
                uint32_t ah[4] = {__float_as_uint(Qh[a0]), __float_as_uint(Qh[a1]),
                                  __float_as_uint(Qh[a0 + 4]), __float_as_uint(Qh[a1 + 4])};
                uint32_t al[4] = {__float_as_uint(Ql[a0]), __float_as_uint(Ql[a1]),
                                  __float_as_uint(Ql[a0 + 4]), __float_as_uint(Ql[a1 + 4])};
#pragma unroll
                for (int nt = 0; nt < 8; nt++) {
                    int boff = (nt * 8 + lq) * 36 + ks * 8 + lr;
                    uint32_t bh[2] = {__float_as_uint(Kh[boff]),
                                      __float_as_uint(Kh[boff + 4])};
                    uint32_t bl[2] = {__float_as_uint(Kl[boff]),
                                      __float_as_uint(Kl[boff + 4])};
                    mma_tf32(sc[nt], ah, bh);
                    mma_tf32(sc[nt], al, bh);
                    mma_tf32(sc[nt], ah, bl);
                }
            }
        }

        // ================== causal mask (diagonal region only) ============
        if (j0 + 64 > q0g) {
            int rg0 = q0g + wm + lq;
            int rg1 = rg0 + 8;
#pragma unroll
            for (int nt = 0; nt < 8; nt++) {
                int cg = j0 + nt * 8 + lr * 2;
                if (cg     > rg0) sc[nt][0] = -1e30f;
                if (cg + 1 > rg0) sc[nt][1] = -1e30f;
                if (cg     > rg1) sc[nt][2] = -1e30f;
                if (cg + 1 > rg1) sc[nt][3] = -1e30f;
            }
        }

        // ================== online softmax (2 rows per thread) ============
        float mx0 = -1e30f, mx1 = -1e30f;
#pragma unroll
        for (int nt = 0; nt < 8; nt++) {
            mx0 = fmaxf(mx0, fmaxf(sc[nt][0], sc[nt][1]));
            mx1 = fmaxf(mx1, fmaxf(sc[nt][2], sc[nt][3]));
        }
        mx0 = fmaxf(mx0, __shfl_xor_sync(0xffffffffu, mx0, 1));
        mx0 = fmaxf(mx0, __shfl_xor_sync(0xffffffffu, mx0, 2));
        mx1 = fmaxf(mx1, __shfl_xor_sync(0xffffffffu, mx1, 1));
        mx1 = fmaxf(mx1, __shfl_xor_sync(0xffffffffu, mx1, 2));
        float mn0 = fmaxf(m_i[0], mx0), mn1 = fmaxf(m_i[1], mx1);
        float al0 = __expf(m_i[0] - mn0), al1 = __expf(m_i[1] - mn1);
        float rs0 = 0.0f, rs1 = 0.0f;
#pragma unroll
        for (int nt = 0; nt < 8; nt++) {
            sc[nt][0] = __expf(sc[nt][0] - mn0);
            sc[nt][1] = __expf(sc[nt][1] - mn0);
            sc[nt][2] = __expf(sc[nt][2] - mn1);
            sc[nt][3] = __expf(sc[nt][3] - mn1);
            rs0 += sc[nt][0] + sc[nt][1];
            rs1 += sc[nt][2] + sc[nt][3];
        }
        rs0 += __shfl_xor_sync(0xffffffffu, rs0, 1);
        rs0 += __shfl_xor_sync(0xffffffffu, rs0, 2);
        rs1 += __shfl_xor_sync(0xffffffffu, rs1, 1);
        rs1 += __shfl_xor_sync(0xffffffffu, rs1, 2);
        l_i[0] = l_i[0] * al0 + rs0; m_i[0] = mn0;
        l_i[1] = l_i[1] * al1 + rs1; m_i[1] = mn1;
#pragma unroll
        for (int nt = 0; nt < 16; nt++) {
            oc[nt][0] *= al0; oc[nt][1] *= al0;
            oc[nt][2] *= al1; oc[nt][3] *= al1;
        }

        // ================== write P (single tf32) =========================
        {
            int r0 = wm + lq, r1 = r0 + 8;
#pragma unroll
            for (int nt = 0; nt < 8; nt++) {
                int c = nt * 8 + lr * 2;
                *(float2*)(Ps + r0 * 68 + c) =
                    make_float2(__uint_as_float(f2tf32(sc[nt][0])),
                                __uint_as_float(f2tf32(sc[nt][1])));
                *(float2*)(Ps + r1 * 68 + c) =
                    make_float2(__uint_as_float(f2tf32(sc[nt][2])),
                                __uint_as_float(f2tf32(sc[nt][3])));
            }
        }

        // ================== O += P @ V  (plain tf32, K=64 in 2 chunks) ====
#pragma unroll
        for (int jc = 0; jc < 2; jc++) {
            __syncthreads();   // prior Vt readers done; P visible
#pragma unroll
            for (int jj = 0; jj < 16; jj++) {
                int jr = jh + jj;
                float v = Vb[(size_t)(j0 + jc * 32 + jr) * KVDIM + dcol];
                Vt[dcol * 36 + jr] = __uint_as_float(f2tf32(v));
            }
            __syncthreads();
#pragma unroll
            for (int ks = 0; ks < 4; ks++) {
                int kp = jc * 32 + ks * 8;
                int a0 = (wm + lq) * 68 + kp + lr;
                int a1 = (wm + lq + 8) * 68 + kp + lr;
                uint32_t a[4] = {__float_as_uint(Ps[a0]), __float_as_uint(Ps[a1]),
                                 __float_as_uint(Ps[a0 + 4]), __float_as_uint(Ps[a1 + 4])};
#pragma unroll
                for (int nt = 0; nt < 16; nt++) {
                    int boff = (nt * 8 + lq) * 36 + ks * 8 + lr;
                    uint32_t bb[2] = {__float_as_uint(Vt[boff]),
                                      __float_as_uint(Vt[boff + 4])};
                    mma_tf32(oc[nt], a, bb);
                }
            }
        }
    }

    // ================== epilogue: normalize + store =======================
    float inv0 = 1.0f / l_i[0], inv1 = 1.0f / l_i[1];
    int r0 = q0g + wm + lq;
#pragma unroll
    for (int nt = 0; nt < 16; nt++) {
        int c = nt * 8 + lr * 2;
        *(float2*)(Ob + (size_t)r0 * HID + c) =
            make_float2(oc[nt][0] * inv0, oc[nt][1] * inv0);
        *(float2*)(Ob + (size_t)(r0 + 8) * HID + c) =
            make_float2(oc[nt][2] * inv1, oc[nt][3] * inv1);
    }
}

// ---------------------------------------------------------------------------
// Launch
// ---------------------------------------------------------------------------
extern "C" void kernel_launch(void* const* d_in, const int* in_sizes, int n_in,
                              void* d_out, int out_size) {
    const float* hidden = (const float*)d_in[0];
    const float* wq = (const float*)d_in[2];
    const float* wk = (const float*)d_in[3];
    const float* wv = (const float*)d_in[4];
    const float* wo = (const float*)d_in[5];
    float*       out = (float*)d_out;

    float *q, *k, *v, *attn, *cosT, *sinT;
    cudaGetSymbolAddress((void**)&q,    g_q);
    cudaGetSymbolAddress((void**)&k,    g_k);
    cudaGetSymbolAddress((void**)&v,    g_v);
    cudaGetSymbolAddress((void**)&attn, g_attn);
    cudaGetSymbolAddress((void**)&cosT, g_cos);
    cudaGetSymbolAddress((void**)&sinT, g_sin);

    cudaFuncSetAttribute(attn_mma_kernel,
                         cudaFuncAttributeMaxDynamicSharedMemorySize,
                         ATTN_SMEM_BYTES);
    cudaFuncSetAttribute(tgemm_comp_kernel,
                         cudaFuncAttributeMaxDynamicSharedMemorySize,
                         CGEMM_SMEM_BYTES);

    // 1. RoPE table
    rope_table_kernel<<<MROWS, 64>>>(cosT, sinT);

    // 2. Projections: Q,K plain tf32; V compensated (feeds output directly)
    tgemm_kernel<<<dim3(HID / 128, MROWS / 128), 256>>>(hidden, wq, q, MROWS, HID, HID);
    tgemm_kernel<<<dim3(KVDIM / 128, MROWS / 128), 256>>>(hidden, wk, k, MROWS, KVDIM, HID);
    tgemm_comp_kernel<<<dim3(KVDIM / 128, MROWS / 128), 256, CGEMM_SMEM_BYTES>>>(
        hidden, wv, v, MROWS, KVDIM, HID);

    // 3. RoPE apply (Q, then K)
    {
        long long tq = (long long)MROWS * NH * 64;
        rope_apply_kernel<<<(unsigned)((tq + 255) / 256), 256>>>(q, cosT, sinT, NH);
        long long tk = (long long)MROWS * KVH * 64;
        rope_apply_kernel<<<(unsigned)((tk + 255) / 256), 256>>>(k, cosT, sinT, KVH);
    }

    // 4. Attention
    attn_mma_kernel<<<dim3(SEQ / 128, NH, BATCH), 256, ATTN_SMEM_BYTES>>>(q, k, v, attn);

    // 5. Output projection (compensated tf32 — feeds output directly)
    tgemm_comp_kernel<<<dim3(HID / 128, MROWS / 128), 256, CGEMM_SMEM_BYTES>>>(
        attn, wo, out, MROWS, HID, HID);
}

// round 12
// speedup vs baseline: 1.3863x; 1.3863x over previous
#include <cuda_runtime.h>
#include <cuda_bf16.h>
#include <math.h>
#include <stdint.h>

// Problem constants
#define BATCH 2
#define SEQ   2048
#define HID   4096
#define NH    32
#define KVH   8
#define HD    128
#define NREP  (NH / KVH)          // 4
#define MROWS (BATCH * SEQ)       // 4096
#define KVDIM (KVH * HD)          // 1024

// ---------------------------------------------------------------------------
// Scratch (device globals; no runtime allocation allowed)
// ---------------------------------------------------------------------------
__device__ float g_q[(size_t)MROWS * NH * HD];      // 64 MB
__device__ float g_k[(size_t)MROWS * KVH * HD];     // 16 MB
__device__ float g_v[(size_t)MROWS * KVH * HD];     // 16 MB
__device__ float g_attn[(size_t)MROWS * HID];       // 64 MB
__device__ float g_cos[(size_t)MROWS * (HD / 2)];
__device__ float g_sin[(size_t)MROWS * (HD / 2)];

// ---------------------------------------------------------------------------
// RoPE cos/sin table. position = row % SEQ (arange broadcast over batch).
// fp64 trig: accurate regardless of --use_fast_math.
// ---------------------------------------------------------------------------
__global__ void rope_table_kernel(float* __restrict__ cosT,
                                  float* __restrict__ sinT) {
    int bs = blockIdx.x;
    int d  = threadIdx.x;      // [0, 64)
    double p = (double)(bs % SEQ);
    double inv_freq = exp(-((double)(2 * d) / 128.0) * log(10000.0));
    double a = p * inv_freq;
    cosT[(size_t)bs * 64 + d] = (float)cos(a);
    sinT[(size_t)bs * 64 + d] = (float)sin(a);
}

// ---------------------------------------------------------------------------
// RoPE apply: x layout [B*S, heads, 128], in-place
// ---------------------------------------------------------------------------
__global__ void rope_apply_kernel(float* __restrict__ x,
                                  const float* __restrict__ cosT,
                                  const float* __restrict__ sinT,
                                  int heads) {
    long long i = (long long)blockIdx.x * blockDim.x + threadIdx.x;
    long long total = (long long)MROWS * heads * 64;
    if (i >= total) return;
    int d = (int)(i & 63);
    long long t = i >> 6;
    int h = (int)(t % heads);
    long long bs = t / heads;
    float c = cosT[bs * 64 + d];
    float s = sinT[bs * 64 + d];
    float* p = x + ((size_t)bs * heads + h) * HD;
    float x1 = p[d];
    float x2 = p[d + 64];
    p[d]      = x1 * c - x2 * s;
    p[d + 64] = x2 * c + x1 * s;
}

// ---------------------------------------------------------------------------
// tf32 helpers
// ---------------------------------------------------------------------------
__device__ __forceinline__ uint32_t f2tf32(float f) {
    uint32_t r;
    asm("cvt.rna.tf32.f32 %0, %1;" : "=r"(r) : "f"(f));
    return r;
}

// Split fp32 into tf32 hi + tf32 lo (hi+lo ~ 21-bit mantissa coverage)
__device__ __forceinline__ void split_tf32(float x, uint32_t& h, uint32_t& l) {
    uint32_t hh = f2tf32(x);
    h = hh;
    l = f2tf32(x - __uint_as_float(hh));
}

__device__ __forceinline__ void mma_tf32(float c[4], const uint32_t a[4],
                                         const uint32_t b[2]) {
    asm volatile(
        "mma.sync.aligned.m16n8k8.row.col.f32.tf32.tf32.f32 "
        "{%0,%1,%2,%3}, {%4,%5,%6,%7}, {%8,%9}, {%0,%1,%2,%3};"
        : "+f"(c[0]), "+f"(c[1]), "+f"(c[2]), "+f"(c[3])
        : "r"(a[0]), "r"(a[1]), "r"(a[2]), "r"(a[3]), "r"(b[0]), "r"(b[1]));
}

// ---------------------------------------------------------------------------
// Plain tf32 GEMM: C[M,N] = A[M,K] @ B[K,N], row-major.
// 128x128 CTA tile, BK=32, 256 threads (8 warps), warp tile 64x32.
// ---------------------------------------------------------------------------
#define AS_STRIDE 36    // 32 + 4  -> conflict-free A-fragment LDS
#define BS_STRIDE 136   // 128 + 8 -> conflict-free B-fragment LDS

__global__ __launch_bounds__(256)
void tgemm_kernel(const float* __restrict__ A, const float* __restrict__ B,
                  float* __restrict__ C, int M, int N, int K) {
    __shared__ uint32_t As[128 * AS_STRIDE];   // [m][k]
    __shared__ uint32_t Bs[32 * BS_STRIDE];    // [k][n]

    const int tid  = threadIdx.x;
    const int lane = tid & 31;
    const int warp = tid >> 5;
    const int wm0 = (warp & 1) * 64;
    const int wn0 = (warp >> 1) * 32;
    const int m0 = blockIdx.y * 128;
    const int n0 = blockIdx.x * 128;
    const int lq = lane >> 2;
    const int lr = lane & 3;

    float c[4][4][4];
#pragma unroll
    for (int mi = 0; mi < 4; mi++)
#pragma unroll
        for (int ni = 0; ni < 4; ni++)
#pragma unroll
            for (int r = 0; r < 4; r++) c[mi][ni][r] = 0.0f;

    for (int kt = 0; kt < K; kt += 32) {
#pragma unroll
        for (int l = 0; l < 4; l++) {
            int idx = tid + l * 256;
            int row = idx >> 3;
            int cc  = (idx & 7) * 4;
            float4 v = *(const float4*)(A + (size_t)(m0 + row) * K + kt + cc);
            uint32_t* p = &As[row * AS_STRIDE + cc];
            p[0] = f2tf32(v.x); p[1] = f2tf32(v.y);
            p[2] = f2tf32(v.z); p[3] = f2tf32(v.w);
        }
#pragma unroll
        for (int l = 0; l < 4; l++) {
            int idx = tid + l * 256;
            int row = idx >> 5;
            int cc  = (idx & 31) * 4;
            float4 v = *(const float4*)(B + (size_t)(kt + row) * N + n0 + cc);
            uint32_t* p = &Bs[row * BS_STRIDE + cc];
            p[0] = f2tf32(v.x); p[1] = f2tf32(v.y);
            p[2] = f2tf32(v.z); p[3] = f2tf32(v.w);
        }
        __syncthreads();

#pragma unroll
        for (int kk = 0; kk < 32; kk += 8) {
            uint32_t a[4][4], b[4][2];
#pragma unroll
            for (int mi = 0; mi < 4; mi++) {
                int rb = wm0 + mi * 16 + lq;
                a[mi][0] = As[rb * AS_STRIDE + kk + lr];
                a[mi][1] = As[(rb + 8) * AS_STRIDE + kk + lr];
                a[mi][2] = As[rb * AS_STRIDE + kk + lr + 4];
                a[mi][3] = As[(rb + 8) * AS_STRIDE + kk + lr + 4];
            }
#pragma unroll
            for (int ni = 0; ni < 4; ni++) {
                int cb = wn0 + ni * 8 + lq;
                b[ni][0] = Bs[(kk + lr) * BS_STRIDE + cb];
                b[ni][1] = Bs[(kk + lr + 4) * BS_STRIDE + cb];
            }
#pragma unroll
            for (int mi = 0; mi < 4; mi++)
#pragma unroll
                for (int ni = 0; ni < 4; ni++)
                    mma_tf32(c[mi][ni], a[mi], b[ni]);
        }
        __syncthreads();
    }

#pragma unroll
    for (int mi = 0; mi < 4; mi++) {
#pragma unroll
        for (int ni = 0; ni < 4; ni++) {
            int r   = m0 + wm0 + mi * 16 + lq;
            int col = n0 + wn0 + ni * 8 + lr * 2;
            *(float2*)(C + (size_t)r * N + col) =
                make_float2(c[mi][ni][0], c[mi][ni][1]);
            *(float2*)(C + (size_t)(r + 8) * N + col) =
                make_float2(c[mi][ni][2], c[mi][ni][3]);
        }
    }
}

// ---------------------------------------------------------------------------
// Flash attention, compensated-tf32 MMA, SOFTWARE PIPELINED.
// BM=128, BN=64, D=128. Grid (SEQ/128, NH, BATCH), 256 threads (8 warps),
// each warp owns 16 rows. S and PV both compensated (hi/lo, 3 MMAs).
// K chunks double-buffered with register prefetch; V prefetched into
// registers under the softmax. 7 syncthreads/tile (was 12), no exposed
// gmem latency.
// Dynamic smem (floats):
//   Qs[128][132] 16896 | Kh/Kl x2 bufs 4x2304 | Psh/Psl 2x8704
//   Vth/Vtl [128][36] 2x4608   -> 52736 fl = 210944 B
// ---------------------------------------------------------------------------
#define ATTN_SMEM_BYTES 210944

__global__ __launch_bounds__(256)
void attn_mma_kernel(const float* __restrict__ Q, const float* __restrict__ K,
                     const float* __restrict__ V, float* __restrict__ O) {
    extern __shared__ float sm[];
    float* Qs  = sm;                 // [128][132] fp32 (scaled)
    float* Kh0 = Qs + 16896;         // [64][36] x2 bufs hi
    float* Kl0 = Kh0 + 2304;
    float* Kh1 = Kl0 + 2304;
    float* Kl1 = Kh1 + 2304;
    float* Psh = Kl1 + 2304;         // [128][68]
    float* Psl = Psh + 8704;
    float* Vth = Psl + 8704;         // [128][36]
    float* Vtl = Vth + 4608;

    float* KhB[2] = {Kh0, Kh1};
    float* KlB[2] = {Kl0, Kl1};

    // longest CTAs first (largest q-tile does most KV tiles)
    const int qi  = gridDim.x - 1 - blockIdx.x;
    const int q0g = qi * 128;
    const int h   = blockIdx.y;
    const int b   = blockIdx.z;
    const int kvh = h / NREP;
    const float* Qb = Q + ((size_t)b * SEQ * NH + h) * HD;
    const float* Kb = K + ((size_t)b * SEQ * KVH + kvh) * HD;
    const float* Vb = V + ((size_t)b * SEQ * KVH + kvh) * HD;
    float* Ob = O + (size_t)b * SEQ * HID + (size_t)h * HD;

    const int tid  = threadIdx.x;
    const int lane = tid & 31;
    const int warp = tid >> 5;
    const int wm   = warp * 16;
    const int lq   = lane >> 2;
    const int lr   = lane & 3;
    const float scale = 0.08838834764831845f;  // 1/sqrt(128)

    // K-chunk load geometry: chunk = 64 rows x 32 cols, 2 float4 per thread
    const int krow0 = tid >> 3;               // 0..31
    const int kcol0 = (tid & 7) * 4;
    const int krow1 = (tid + 256) >> 3;       // 32..63
    const int kcol1 = kcol0;

    // V load geometry
    const int dcol = tid & 127;
    const int jh   = (tid >> 7) * 16;

    // ---- load Q tile once (scaled, fp32; split per-fragment in regs) ----
#pragma unroll
    for (int l = 0; l < 16; l++) {
        int idx = tid + l * 256;
        int row = idx >> 5;
        int c4  = (idx & 31) * 4;
        float4 v = *(const float4*)(Qb + (size_t)(q0g + row) * (NH * HD) + c4);
        float* p = Qs + row * 132 + c4;
        p[0] = v.x * scale; p[1] = v.y * scale;
        p[2] = v.z * scale; p[3] = v.w * scale;
    }

    float oc[16][4];
#pragma unroll
    for (int nt = 0; nt < 16; nt++)
#pragma unroll
        for (int r = 0; r < 4; r++) oc[nt][r] = 0.0f;
    float m_i[2] = {-1e30f, -1e30f};
    float l_i[2] = {0.0f, 0.0f};

    const int jmax = q0g + 64;
    for (int j0 = 0; j0 <= jmax; j0 += 64) {
        const float* Kt = Kb + (size_t)j0 * KVDIM;
        const float* Vt0 = Vb + (size_t)j0 * KVDIM;

        // ================== S = Qscaled @ K^T  (pipelined K chunks) =======
        float sc[8][4];
#pragma unroll
        for (int nt = 0; nt < 8; nt++)
#pragma unroll
            for (int r = 0; r < 4; r++) sc[nt][r] = 0.0f;

        // preload chunk 0 into registers
        float4 kra = *(const float4*)(Kt + (size_t)krow0 * KVDIM + kcol0);
        float4 krb = *(const float4*)(Kt + (size_t)krow1 * KVDIM + kcol1);

#pragma unroll
        for (int kc = 0; kc < 4; kc++) {
            // STS current chunk (split hi/lo). Buffer reuse safe: last
            // reader of this buffer synced at kc-1's barrier (or prev tile).
            float* ph = KhB[kc & 1];
            float* pl = KlB[kc & 1];
            {
                uint32_t hh, ll;
                float* p0h = ph + krow0 * 36 + kcol0;
                float* p0l = pl + krow0 * 36 + kcol0;
                split_tf32(kra.x, hh, ll); p0h[0] = __uint_as_float(hh); p0l[0] = __uint_as_float(ll);
                split_tf32(kra.y, hh, ll); p0h[1] = __uint_as_float(hh); p0l[1] = __uint_as_float(ll);
                split_tf32(kra.z, hh, ll); p0h[2] = __uint_as_float(hh); p0l[2] = __uint_as_float(ll);
                split_tf32(kra.w, hh, ll); p0h[3] = __uint_as_float(hh); p0l[3] = __uint_as_float(ll);
                float* p1h = ph + krow1 * 36 + kcol1;
                float* p1l = pl + krow1 * 36 + kcol1;
                split_tf32(krb.x, hh, ll); p1h[0] = __uint_as_float(hh); p1l[0] = __uint_as_float(ll);
                split_tf32(krb.y, hh, ll); p1h[1] = __uint_as_float(hh); p1l[1] = __uint_as_float(ll);
                split_tf32(krb.z, hh, ll); p1h[2] = __uint_as_float(hh); p1l[2] = __uint_as_float(ll);
                split_tf32(krb.w, hh, ll); p1h[3] = __uint_as_float(hh); p1l[3] = __uint_as_float(ll);
            }
            __syncthreads();
            // prefetch next chunk (latency hidden by MMAs below)
            if (kc < 3) {
                kra = *(const float4*)(Kt + (size_t)krow0 * KVDIM + (kc + 1) * 32 + kcol0);
                krb = *(const float4*)(Kt + (size_t)krow1 * KVDIM + (kc + 1) * 32 + kcol1);
            }
            // MMAs on this chunk
#pragma unroll
            for (int ks = 0; ks < 4; ks++) {
                int kq = kc * 32 + ks * 8;
                const float* q0p = Qs + (wm + lq) * 132 + kq + lr;
                const float* q1p = Qs + (wm + lq + 8) * 132 + kq + lr;
                uint32_t ah[4], al[4];
                split_tf32(q0p[0], ah[0], al[0]);
                split_tf32(q1p[0], ah[1], al[1]);
                split_tf32(q0p[4], ah[2], al[2]);
                split_tf32(q1p[4], ah[3], al[3]);
#pragma unroll
                for (int nt = 0; nt < 8; nt++) {
                    int boff = (nt * 8 + lq) * 36 + ks * 8 + lr;
                    uint32_t bh[2] = {__float_as_uint(ph[boff]),
                                      __float_as_uint(ph[boff + 4])};
                    uint32_t bl[2] = {__float_as_uint(pl[boff]),
                                      __float_as_uint(pl[boff + 4])};
                    mma_tf32(sc[nt], ah, bh);
                    mma_tf32(sc[nt], al, bh);
                    mma_tf32(sc[nt], ah, bl);
                }
            }
        }

        // prefetch V chunk 0 (rows j0..j0+31) — hidden under softmax
        float vreg[16];
#pragma unroll
        for (int jj = 0; jj < 16; jj++)
            vreg[jj] = Vt0[(size_t)(jh + jj) * KVDIM + dcol];

        // ================== causal mask (diagonal region only) ============
        if (j0 + 64 > q0g) {
            int rg0 = q0g + wm + lq;
            int rg1 = rg0 + 8;
#pragma unroll
            for (int nt = 0; nt < 8; nt++) {
                int cg = j0 + nt * 8 + lr * 2;
                if (cg     > rg0) sc[nt][0] = -1e30f;
                if (cg + 1 > rg0) sc[nt][1] = -1e30f;
                if (cg     > rg1) sc[nt][2] = -1e30f;
                if (cg + 1 > rg1) sc[nt][3] = -1e30f;
            }
        }

        // ================== online softmax (2 rows per thread) ============
        float mx0 = -1e30f, mx1 = -1e30f;
#pragma unroll
        for (int nt = 0; nt < 8; nt++) {
            mx0 = fmaxf(mx0, fmaxf(sc[nt][0], sc[nt][1]));
            mx1 = fmaxf(mx1, fmaxf(sc[nt][2], sc[nt][3]));
        }
        mx0 = fmaxf(mx0, __shfl_xor_sync(0xffffffffu, mx0, 1));
        mx0 = fmaxf(mx0, __shfl_xor_sync(0xffffffffu, mx0, 2));
        mx1 = fmaxf(mx1, __shfl_xor_sync(0xffffffffu, mx1, 1));
        mx1 = fmaxf(mx1, __shfl_xor_sync(0xffffffffu, mx1, 2));
        float mn0 = fmaxf(m_i[0], mx0), mn1 = fmaxf(m_i[1], mx1);
        float al0 = __expf(m_i[0] - mn0), al1 = __expf(m_i[1] - mn1);
        float rs0 = 0.0f, rs1 = 0.0f;
#pragma unroll
        for (int nt = 0; nt < 8; nt++) {
            sc[nt][0] = __expf(sc[nt][0] - mn0);
            sc[nt][1] = __expf(sc[nt][1] - mn0);
            sc[nt][2] = __expf(sc[nt][2] - mn1);
            sc[nt][3] = __expf(sc[nt][3] - mn1);
            rs0 += sc[nt][0] + sc[nt][1];
            rs1 += sc[nt][2] + sc[nt][3];
        }
        rs0 += __shfl_xor_sync(0xffffffffu, rs0, 1);
        rs0 += __shfl_xor_sync(0xffffffffu, rs0, 2);
        rs1 += __shfl_xor_sync(0xffffffffu, rs1, 1);
        rs1 += __shfl_xor_sync(0xffffffffu, rs1, 2);
        l_i[0] = l_i[0] * al0 + rs0; m_i[0] = mn0;
        l_i[1] = l_i[1] * al1 + rs1; m_i[1] = mn1;
#pragma unroll
        for (int nt = 0; nt < 16; nt++) {
            oc[nt][0] *= al0; oc[nt][1] *= al0;
            oc[nt][2] *= al1; oc[nt][3] *= al1;
        }

        // ================== write P (hi/lo) — warp-private rows ===========
        {
            int r0 = wm + lq, r1 = r0 + 8;
#pragma unroll
            for (int nt = 0; nt < 8; nt++) {
                int c = nt * 8 + lr * 2;
                uint32_t h0, l0, h1, l1;
                split_tf32(sc[nt][0], h0, l0);
                split_tf32(sc[nt][1], h1, l1);
                *(float2*)(Psh + r0 * 68 + c) =
                    make_float2(__uint_as_float(h0), __uint_as_float(h1));
                *(float2*)(Psl + r0 * 68 + c) =
                    make_float2(__uint_as_float(l0), __uint_as_float(l1));
                split_tf32(sc[nt][2], h0, l0);
                split_tf32(sc[nt][3], h1, l1);
                *(float2*)(Psh + r1 * 68 + c) =
                    make_float2(__uint_as_float(h0), __uint_as_float(h1));
                *(float2*)(Psl + r1 * 68 + c) =
                    make_float2(__uint_as_float(l0), __uint_as_float(l1));
            }
        }

        // ================== O += P @ V  (pipelined V chunks) ==============
#pragma unroll
        for (int jc = 0; jc < 2; jc++) {
            // STS V chunk (split hi/lo); buffer last read covered by syncs
            __syncthreads();   // all warps done reading Vt (prev chunk/tile)
#pragma unroll
            for (int jj = 0; jj < 16; jj++) {
                uint32_t hh, ll;
                split_tf32(vreg[jj], hh, ll);
                Vth[dcol * 36 + jh + jj] = __uint_as_float(hh);
                Vtl[dcol * 36 + jh + jj] = __uint_as_float(ll);
            }
            __syncthreads();
            // prefetch V chunk 1 during chunk-0 MMAs
            if (jc == 0) {
#pragma unroll
                for (int jj = 0; jj < 16; jj++)
                    vreg[jj] = Vt0[(size_t)(32 + jh + jj) * KVDIM + dcol];
            }
#pragma unroll
            for (int ks = 0; ks < 4; ks++) {
                int kp = jc * 32 + ks * 8;
                int a0 = (wm + lq) * 68 + kp + lr;
                int a1 = (wm + lq + 8) * 68 + kp + lr;
                uint32_t ah[4] = {__float_as_uint(Psh[a0]), __float_as_uint(Psh[a1]),
                                  __float_as_uint(Psh[a0 + 4]), __float_as_uint(Psh[a1 + 4])};
                uint32_t al[4] = {__float_as_uint(Psl[a0]), __float_as_uint(Psl[a1]),
                                  __float_as_uint(Psl[a0 + 4]), __float_as_uint(Psl[a1 + 4])};
#pragma unroll
                for (int nt = 0; nt < 16; nt++) {
                    int boff = (nt * 8 + lq) * 36 + ks * 8 + lr;
                    uint32_t bh[2] = {__float_as_uint(Vth[boff]),
                                      __float_as_uint(Vth[boff + 4])};
                    uint32_t bl[2] = {__float_as_uint(Vtl[boff]),
                                      __float_as_uint(Vtl[boff + 4])};
                    mma_tf32(oc[nt], ah, bh);
                    mma_tf32(oc[nt], al, bh);
                    mma_tf32(oc[nt], ah, bl);
                }
            }
        }
        __syncthreads();   // Vt/K-buf readers done before next tile's writes
    }

    // ================== epilogue: normalize + store =======================
    float inv0 = 1.0f / l_i[0], inv1 = 1.0f / l_i[1];
    int r0 = q0g + wm + lq;
#pragma unroll
    for (int nt = 0; nt < 16; nt++) {
        int c = nt * 8 + lr * 2;
        *(float2*)(Ob + (size_t)r0 * HID + c) =
            make_float2(oc[nt][0] * inv0, oc[nt][1] * inv0);
        *(float2*)(Ob + (size_t)(r0 + 8) * HID + c) =
            make_float2(oc[nt][2] * inv1, oc[nt][3] * inv1);
    }
}

// ---------------------------------------------------------------------------
// Launch
// ---------------------------------------------------------------------------
extern "C" void kernel_launch(void* const* d_in, const int* in_sizes, int n_in,
                              void* d_out, int out_size) {
    const float* hidden = (const float*)d_in[0];
    const float* wq = (const float*)d_in[2];
    const float* wk = (const float*)d_in[3];
    const float* wv = (const float*)d_in[4];
    const float* wo = (const float*)d_in[5];
    float*       out = (float*)d_out;

    float *q, *k, *v, *attn, *cosT, *sinT;
    cudaGetSymbolAddress((void**)&q,    g_q);
    cudaGetSymbolAddress((void**)&k,    g_k);
    cudaGetSymbolAddress((void**)&v,    g_v);
    cudaGetSymbolAddress((void**)&attn, g_attn);
    cudaGetSymbolAddress((void**)&cosT, g_cos);
    cudaGetSymbolAddress((void**)&sinT, g_sin);

    cudaFuncSetAttribute(attn_mma_kernel,
                         cudaFuncAttributeMaxDynamicSharedMemorySize,
                         ATTN_SMEM_BYTES);

    // 1. RoPE table
    rope_table_kernel<<<MROWS, 64>>>(cosT, sinT);

    // 2. QKV projections (plain tf32 tensor cores)
    tgemm_kernel<<<dim3(HID / 128, MROWS / 128), 256>>>(hidden, wq, q, MROWS, HID, HID);
    tgemm_kernel<<<dim3(KVDIM / 128, MROWS / 128), 256>>>(hidden, wk, k, MROWS, KVDIM, HID);
    tgemm_kernel<<<dim3(KVDIM / 128, MROWS / 128), 256>>>(hidden, wv, v, MROWS, KVDIM, HID);

    // 3. RoPE apply (Q, then K)
    {
        long long tq = (long long)MROWS * NH * 64;
        rope_apply_kernel<<<(unsigned)((tq + 255) / 256), 256>>>(q, cosT, sinT, NH);
        long long tk = (long long)MROWS * KVH * 64;
        rope_apply_kernel<<<(unsigned)((tk + 255) / 256), 256>>>(k, cosT, sinT, KVH);
    }

    // 4. Attention (pipelined compensated tf32 MMA flash attention)
    attn_mma_kernel<<<dim3(SEQ / 128, NH, BATCH), 256, ATTN_SMEM_BYTES>>>(q, k, v, attn);

    // 5. Output projection (plain tf32 tensor cores)
    tgemm_kernel<<<dim3(HID / 128, MROWS / 128), 256>>>(attn, wo, out, MROWS, HID, HID);
}